// round 9
// baseline (speedup 1.0000x reference)
#include <cuda_runtime.h>
#include <cuda_bf16.h>
#include <cstdint>

// GrahamLoss via S/T factorization, single kernel, legacy bf16 mma.sync.
// S=F+D, T=D-F  =>  D D^T - F F^T = (S T^T + T S^T)/2 (exact identity).
// CTA (I,J), I<=J over 8x8 grid of 64-row blocks: computes P=S_I T_J^T and
// Q=S_J T_I^T (64x64 each), pairs P with Q^T via smem, squares, reduces.

#define B_    16
#define C_    512
#define HW_   1024
#define KC    64             // fp32 k per chunk
#define NCH   (HW_ / KC)     // 16
#define NT2   36             // 8x8 upper triangle
#define NPART (B_ * NT2)     // 576

// bf16 panels: 64 rows x 64 cols, stored as 2 sub-panels of 64B rows
#define OSI 0
#define OTI 8192
#define OSJ 16384
#define OTJ 24576
#define STG 32768
#define DYN_SMEM 65536

__device__ float        g_partials[NPART];
__device__ unsigned int g_count;

__constant__ int c_u[NT2] = {0,0,0,0,0,0,0,0,1,1,1,1,1,1,1,2,2,2,2,2,2,3,3,3,3,3,4,4,4,4,5,5,5,6,6,7};
__constant__ int c_v[NT2] = {0,1,2,3,4,5,6,7,1,2,3,4,5,6,7,2,3,4,5,6,7,3,4,5,6,7,4,5,6,7,5,6,7,6,7,7};

// ---------- helpers ----------
__device__ __forceinline__ uint32_t smem_u32(const void* p) {
    uint32_t a;
    asm("{ .reg .u64 t; cvta.to.shared.u64 t, %1; cvt.u32.u64 %0, t; }" : "=r"(a) : "l"(p));
    return a;
}
// panel address for bf16 col k in [0,64): sub-panel (k>>5), 64B rows, XOR swizzle
__device__ __forceinline__ uint32_t paddr(uint32_t pbase, int row, int k) {
    return pbase + ((uint32_t)(k >> 5) << 12) + (uint32_t)row * 64u
         + ((((uint32_t)(k >> 3) ^ (uint32_t)(row >> 1)) & 3u) << 4) + ((uint32_t)(k & 7) << 1);
}
__device__ __forceinline__ uint32_t pack2(float hi, float lo) {
    uint32_t r;
    asm("cvt.rn.bf16x2.f32 %0, %1, %2;" : "=r"(r) : "f"(hi), "f"(lo));
    return r;
}
__device__ __forceinline__ void sts64(uint32_t addr, uint32_t a, uint32_t b) {
    asm volatile("st.shared.v2.b32 [%0], {%1, %2};" :: "r"(addr), "r"(a), "r"(b) : "memory");
}
__device__ __forceinline__ void ldm_x4(uint32_t* r, uint32_t addr) {
    asm volatile("ldmatrix.sync.aligned.m8n8.x4.shared.b16 {%0,%1,%2,%3}, [%4];"
                 : "=r"(r[0]), "=r"(r[1]), "=r"(r[2]), "=r"(r[3]) : "r"(addr));
}
__device__ __forceinline__ void mma_bf16(float* d, const uint32_t* a, const uint32_t* b) {
    asm volatile("mma.sync.aligned.m16n8k16.row.col.f32.bf16.bf16.f32 "
                 "{%0,%1,%2,%3}, {%4,%5,%6,%7}, {%8,%9}, {%0,%1,%2,%3};"
                 : "+f"(d[0]), "+f"(d[1]), "+f"(d[2]), "+f"(d[3])
                 : "r"(a[0]), "r"(a[1]), "r"(a[2]), "r"(a[3]), "r"(b[0]), "r"(b[1]));
}

struct FragP { uint32_t a[2][4]; uint32_t b[2][2]; };

__device__ __forceinline__ void ld_fr(uint32_t pA, int arow0, uint32_t pB, int brow0,
                                      int k0, int lane, FragP& f) {
    const int a_row = lane & 15;
    const int a_k   = (lane >> 4) << 3;
    ldm_x4(f.a[0], paddr(pA, arow0 + a_row,      k0 + a_k));
    ldm_x4(f.a[1], paddr(pA, arow0 + 16 + a_row, k0 + a_k));
    const int b_row = (((lane >> 4) & 1) << 3) + (lane & 7);
    const int b_k   = ((lane >> 3) & 1) << 3;
    uint32_t t4[4];
    ldm_x4(t4, paddr(pB, brow0 + b_row, k0 + b_k));
    f.b[0][0] = t4[0]; f.b[0][1] = t4[1];
    f.b[1][0] = t4[2]; f.b[1][1] = t4[3];
}
__device__ __forceinline__ void mma_fr(float acc[2][2][4], const FragP& f) {
    #pragma unroll
    for (int mt = 0; mt < 2; mt++)
        #pragma unroll
        for (int nt = 0; nt < 2; nt++)
            mma_bf16(acc[mt][nt], f.a[mt], f.b[nt]);
}
// one 32(m) x 16(n) x 64(k) warp-unit over a chunk, frag double-buffered
__device__ __forceinline__ void unit_chunk(uint32_t pA, int arow0, uint32_t pB, int brow0,
                                           int lane, float acc[2][2][4]) {
    FragP f0, f1;
    ld_fr(pA, arow0, pB, brow0, 0,  lane, f0);
    ld_fr(pA, arow0, pB, brow0, 16, lane, f1);
    mma_fr(acc, f0);
    ld_fr(pA, arow0, pB, brow0, 32, lane, f0);
    mma_fr(acc, f1);
    ld_fr(pA, arow0, pB, brow0, 48, lane, f1);
    mma_fr(acc, f0);
    mma_fr(acc, f1);
}

// ---------- main kernel ----------
__global__ __launch_bounds__(256, 2)
void gram_st_kernel(const float* __restrict__ F, const float* __restrict__ Dm,
                    float* __restrict__ out) {
    extern __shared__ __align__(128) unsigned char smem[];
    __shared__ float red[256];
    __shared__ unsigned int s_islast;

    const int tid  = threadIdx.x;
    const int lane = tid & 31;
    const int wid  = tid >> 5;
    const int b    = blockIdx.y;
    const int I = c_u[blockIdx.x];
    const int J = c_v[blockIdx.x];
    const int diag = (I == J);
    const float w = diag ? 1.0f : 2.0f;

    const float* FIg = F  + ((size_t)b * C_ + I * 64) * HW_;
    const float* DIg = Dm + ((size_t)b * C_ + I * 64) * HW_;
    const float* FJg = F  + ((size_t)b * C_ + J * 64) * HW_;
    const float* DJg = Dm + ((size_t)b * C_ + J * 64) * HW_;

    const uint32_t sbase = smem_u32(smem);

    // warp tiling: 2(m) x 4(n), warp tile 32x16 over 64x64
    const int wm = wid >> 2;
    const int wn = wid & 3;
    const int arow0 = wm * 32;
    const int brow0 = wn * 16;

    // producer slot mapping: slot = tid + j*256 -> row = slot>>4, kk = (slot&15)*4
    int      goff[4];
    uint32_t soff[4];
    #pragma unroll
    for (int j = 0; j < 4; j++) {
        int slot = tid + j * 256;
        int row = slot >> 4, kk = (slot & 15) * 4;
        goff[j] = row * HW_ + kk;
        soff[j] = paddr(0, row, kk);
    }

    float accP[2][2][4], accQ[2][2][4];
    #pragma unroll
    for (int mt = 0; mt < 2; mt++)
        #pragma unroll
        for (int nt = 0; nt < 2; nt++)
            #pragma unroll
            for (int r = 0; r < 4; r++) { accP[mt][nt][r] = 0.f; accQ[mt][nt][r] = 0.f; }

    // ---- prologue: chunk 0 -> stage 0 ----
    #pragma unroll
    for (int j = 0; j < 4; j++) {
        float4 f = *(const float4*)(FIg + goff[j]);
        float4 d = *(const float4*)(DIg + goff[j]);
        float4 s = make_float4(f.x + d.x, f.y + d.y, f.z + d.z, f.w + d.w);
        float4 t = make_float4(d.x - f.x, d.y - f.y, d.z - f.z, d.w - f.w);
        sts64(sbase + OSI + soff[j], pack2(s.y, s.x), pack2(s.w, s.z));
        sts64(sbase + OTI + soff[j], pack2(t.y, t.x), pack2(t.w, t.z));
    }
    if (!diag) {
        #pragma unroll
        for (int j = 0; j < 4; j++) {
            float4 f = *(const float4*)(FJg + goff[j]);
            float4 d = *(const float4*)(DJg + goff[j]);
            float4 s = make_float4(f.x + d.x, f.y + d.y, f.z + d.z, f.w + d.w);
            float4 t = make_float4(d.x - f.x, d.y - f.y, d.z - f.z, d.w - f.w);
            sts64(sbase + OSJ + soff[j], pack2(s.y, s.x), pack2(s.w, s.z));
            sts64(sbase + OTJ + soff[j], pack2(t.y, t.x), pack2(t.w, t.z));
        }
    }
    __syncthreads();

    // ---- main loop ----
    for (int c = 0; c < NCH; c++) {
        const uint32_t stb  = sbase + (c & 1) * STG;
        const uint32_t nstb = sbase + ((c & 1) ^ 1) * STG;
        const bool more = (c + 1 < NCH);
        const int k1 = (c + 1) * KC;

        float4 rf[4], rd[4];
        if (more) {       // issue I-block loads for next chunk
            #pragma unroll
            for (int j = 0; j < 4; j++) {
                rf[j] = *(const float4*)(FIg + goff[j] + k1);
                rd[j] = *(const float4*)(DIg + goff[j] + k1);
            }
        }
        // P = S_I T_J^T (diag: T_I)
        unit_chunk(stb + OSI, arow0, stb + (diag ? OTI : OTJ), brow0, lane, accP);
        if (more) {       // convert+store I-block; issue J-block loads
            #pragma unroll
            for (int j = 0; j < 4; j++) {
                float4 f = rf[j], d = rd[j];
                float4 s = make_float4(f.x + d.x, f.y + d.y, f.z + d.z, f.w + d.w);
                float4 t = make_float4(d.x - f.x, d.y - f.y, d.z - f.z, d.w - f.w);
                sts64(nstb + OSI + soff[j], pack2(s.y, s.x), pack2(s.w, s.z));
                sts64(nstb + OTI + soff[j], pack2(t.y, t.x), pack2(t.w, t.z));
            }
            if (!diag) {
                #pragma unroll
                for (int j = 0; j < 4; j++) {
                    rf[j] = *(const float4*)(FJg + goff[j] + k1);
                    rd[j] = *(const float4*)(DJg + goff[j] + k1);
                }
            }
        }
        // Q = S_J T_I^T
        if (!diag)
            unit_chunk(stb + OSJ, arow0, stb + OTI, brow0, lane, accQ);
        if (more && !diag) {
            #pragma unroll
            for (int j = 0; j < 4; j++) {
                float4 f = rf[j], d = rd[j];
                float4 s = make_float4(f.x + d.x, f.y + d.y, f.z + d.z, f.w + d.w);
                float4 t = make_float4(d.x - f.x, d.y - f.y, d.z - f.z, d.w - f.w);
                sts64(nstb + OSJ + soff[j], pack2(s.y, s.x), pack2(s.w, s.z));
                sts64(nstb + OTJ + soff[j], pack2(t.y, t.x), pack2(t.w, t.z));
            }
        }
        __syncthreads();
    }

    // ---- epilogue: pair P with Q^T via smem (reuse pipeline smem) ----
    float* sP = (float*)smem;            // 64 x 65
    float* sQ = sP + 64 * 65;
    const int quad = lane >> 2;
    const int tcol = (lane & 3) * 2;
    #pragma unroll
    for (int mt = 0; mt < 2; mt++) {
        #pragma unroll
        for (int nt = 0; nt < 2; nt++) {
            int r0 = wm * 32 + mt * 16 + quad;
            int c0 = wn * 16 + nt * 8 + tcol;
            sP[r0 * 65 + c0]           = accP[mt][nt][0];
            sP[r0 * 65 + c0 + 1]       = accP[mt][nt][1];
            sP[(r0 + 8) * 65 + c0]     = accP[mt][nt][2];
            sP[(r0 + 8) * 65 + c0 + 1] = accP[mt][nt][3];
            const float* src = diag ? accP[mt][nt] : accQ[mt][nt];
            sQ[r0 * 65 + c0]           = src[0];
            sQ[r0 * 65 + c0 + 1]       = src[1];
            sQ[(r0 + 8) * 65 + c0]     = src[2];
            sQ[(r0 + 8) * 65 + c0 + 1] = src[3];
        }
    }
    __syncthreads();

    float local = 0.f;
    #pragma unroll
    for (int i = 0; i < 16; i++) {
        int e = tid + i * 256;
        int r = e >> 6, cc = e & 63;
        float val = 0.5f * (sP[r * 65 + cc] + sQ[cc * 65 + r]);
        local = fmaf(val, val, local);
    }
    local *= w;

    red[tid] = local;
    __syncthreads();
    #pragma unroll
    for (int stp = 128; stp > 0; stp >>= 1) {
        if (tid < stp) red[tid] += red[tid + stp];
        __syncthreads();
    }

    if (tid == 0) {
        g_partials[b * NT2 + blockIdx.x] = red[0];
        __threadfence();
        unsigned int prev = atomicAdd(&g_count, 1u);
        s_islast = (prev == NPART - 1) ? 1u : 0u;
    }
    __syncthreads();
    if (s_islast) {
        __threadfence();
        float v = 0.f;
        for (int i = tid; i < NPART; i += 256) v += g_partials[i];
        red[tid] = v;
        __syncthreads();
        #pragma unroll
        for (int stp = 128; stp > 0; stp >>= 1) {
            if (tid < stp) red[tid] += red[tid + stp];
            __syncthreads();
        }
        if (tid == 0) {
            out[0] = red[0] * (1.0f / 1099511627776.0f);  // / 2^40
            g_count = 0;  // reset for next graph replay
        }
    }
}

extern "C" void kernel_launch(void* const* d_in, const int* in_sizes, int n_in,
                              void* d_out, int out_size) {
    const float* F = (const float*)d_in[0];   // feat
    const float* D = (const float*)d_in[1];   // feat_decod
    float* out = (float*)d_out;

    cudaFuncSetAttribute(gram_st_kernel, cudaFuncAttributeMaxDynamicSharedMemorySize, DYN_SMEM);
    dim3 grid(NT2, B_);
    gram_st_kernel<<<grid, 256, DYN_SMEM>>>(F, D, out);
}

// round 10
// speedup vs baseline: 1.2195x; 1.2195x over previous
#include <cuda_runtime.h>
#include <cuda_bf16.h>
#include <cstdint>

// GrahamLoss via S/T factorization, bf16 mma.sync, P/Q warp-specialized.
// S=F+D, T=D-F  =>  D D^T - F F^T = (S T^T + T S^T)/2 (exact identity).
// CTA (I,J), I<=J over 8x8 grid of 64-row blocks. Warps 0-3: P=S_I T_J^T,
// warps 4-7: Q=S_J T_I^T (32x32 warp tiles). Pair P with Q^T in smem.

#define B_    16
#define C_    512
#define HW_   1024
#define KC    64             // fp32 k per chunk
#define NCH   (HW_ / KC)     // 16
#define NT2   36             // 8x8 upper triangle
#define NPART (B_ * NT2)     // 576

// bf16 panels: 64 rows x 64 cols = 64 rows x 128B (single 128B row, XOR swizzle)
#define OSI 0
#define OTI 8192
#define OSJ 16384
#define OTJ 24576
#define STG 32768
#define DYN_SMEM 65536

__device__ float        g_partials[NPART];
__device__ unsigned int g_count;

__constant__ int c_u[NT2] = {0,0,0,0,0,0,0,0,1,1,1,1,1,1,1,2,2,2,2,2,2,3,3,3,3,3,4,4,4,4,5,5,5,6,6,7};
__constant__ int c_v[NT2] = {0,1,2,3,4,5,6,7,1,2,3,4,5,6,7,2,3,4,5,6,7,3,4,5,6,7,4,5,6,7,5,6,7,6,7,7};

// ---------- helpers ----------
__device__ __forceinline__ uint32_t smem_u32(const void* p) {
    uint32_t a;
    asm("{ .reg .u64 t; cvta.to.shared.u64 t, %1; cvt.u32.u64 %0, t; }" : "=r"(a) : "l"(p));
    return a;
}
// 128B-row panel address, bf16 col k in [0,64): 16B unit XOR row&7 (bank-conflict-free)
__device__ __forceinline__ uint32_t paddr(uint32_t pbase, int row, int k) {
    return pbase + (uint32_t)row * 128u
         + ((((uint32_t)(k >> 3) ^ (uint32_t)row) & 7u) << 4) + ((uint32_t)(k & 7) << 1);
}
__device__ __forceinline__ uint32_t pack2(float hi, float lo) {
    uint32_t r;
    asm("cvt.rn.bf16x2.f32 %0, %1, %2;" : "=r"(r) : "f"(hi), "f"(lo));
    return r;
}
__device__ __forceinline__ void sts64(uint32_t addr, uint32_t a, uint32_t b) {
    asm volatile("st.shared.v2.b32 [%0], {%1, %2};" :: "r"(addr), "r"(a), "r"(b) : "memory");
}
__device__ __forceinline__ void ldm_x4(uint32_t* r, uint32_t addr) {
    asm volatile("ldmatrix.sync.aligned.m8n8.x4.shared.b16 {%0,%1,%2,%3}, [%4];"
                 : "=r"(r[0]), "=r"(r[1]), "=r"(r[2]), "=r"(r[3]) : "r"(addr));
}
__device__ __forceinline__ void mma_bf16(float* d, const uint32_t* a, const uint32_t* b) {
    asm volatile("mma.sync.aligned.m16n8k16.row.col.f32.bf16.bf16.f32 "
                 "{%0,%1,%2,%3}, {%4,%5,%6,%7}, {%8,%9}, {%0,%1,%2,%3};"
                 : "+f"(d[0]), "+f"(d[1]), "+f"(d[2]), "+f"(d[3])
                 : "r"(a[0]), "r"(a[1]), "r"(a[2]), "r"(a[3]), "r"(b[0]), "r"(b[1]));
}

struct Frag { uint32_t a[2][4]; uint32_t b[4][2]; };

// 32x32 warp tile fragments for one k16 step
__device__ __forceinline__ void ld_fr(uint32_t pA, int arow0, uint32_t pB, int brow0,
                                      int k0, int lane, Frag& f) {
    const int a_row = lane & 15;
    const int a_k   = (lane >> 4) << 3;
    ldm_x4(f.a[0], paddr(pA, arow0 + a_row,      k0 + a_k));
    ldm_x4(f.a[1], paddr(pA, arow0 + 16 + a_row, k0 + a_k));
    const int b_row = (((lane >> 4) & 1) << 3) + (lane & 7);
    const int b_k   = ((lane >> 3) & 1) << 3;
    #pragma unroll
    for (int tp = 0; tp < 2; tp++) {
        uint32_t t4[4];
        ldm_x4(t4, paddr(pB, brow0 + tp * 16 + b_row, k0 + b_k));
        f.b[2 * tp][0] = t4[0]; f.b[2 * tp][1] = t4[1];
        f.b[2 * tp + 1][0] = t4[2]; f.b[2 * tp + 1][1] = t4[3];
    }
}
__device__ __forceinline__ void mma_fr(float acc[2][4][4], const Frag& f) {
    #pragma unroll
    for (int mt = 0; mt < 2; mt++)
        #pragma unroll
        for (int nt = 0; nt < 4; nt++)
            mma_bf16(acc[mt][nt], f.a[mt], f.b[nt]);
}

// ---------- main kernel ----------
__global__ __launch_bounds__(256, 2)
void gram_st_kernel(const float* __restrict__ F, const float* __restrict__ Dm,
                    float* __restrict__ out) {
    extern __shared__ __align__(128) unsigned char smem[];
    __shared__ float red[256];
    __shared__ unsigned int s_islast;

    const int tid  = threadIdx.x;
    const int lane = tid & 31;
    const int wid  = tid >> 5;
    const int b    = blockIdx.y;
    const int I = c_u[blockIdx.x];
    const int J = c_v[blockIdx.x];
    const int diag = (I == J);
    const float w = diag ? 1.0f : 2.0f;

    const float* FIg = F  + ((size_t)b * C_ + I * 64) * HW_;
    const float* DIg = Dm + ((size_t)b * C_ + I * 64) * HW_;
    const float* FJg = F  + ((size_t)b * C_ + J * 64) * HW_;
    const float* DJg = Dm + ((size_t)b * C_ + J * 64) * HW_;

    const uint32_t sbase = smem_u32(smem);

    // warp role: 0 => P = S_I T_J^T, 1 => Q = S_J T_I^T ; 2x2 grid of 32x32 tiles
    const int role = wid >> 2;
    const int wq   = wid & 3;
    const int arow0 = (wq >> 1) * 32;
    const int brow0 = (wq & 1) * 32;
    // panel offsets for this warp's role (stage-relative)
    const uint32_t oA = role ? (diag ? OSI : OSJ) : OSI;
    const uint32_t oB = role ? OTI : (diag ? OTI : OTJ);

    // producer slot mapping: slot = tid + j*256 -> row = slot>>4, kk = (slot&15)*4
    int      goff[4];
    uint32_t soff[4];
    #pragma unroll
    for (int j = 0; j < 4; j++) {
        int slot = tid + j * 256;
        int row = slot >> 4, kk = (slot & 15) * 4;
        goff[j] = row * HW_ + kk;
        soff[j] = paddr(0, row, kk);
    }

    float acc[2][4][4];
    #pragma unroll
    for (int mt = 0; mt < 2; mt++)
        #pragma unroll
        for (int nt = 0; nt < 4; nt++)
            #pragma unroll
            for (int r = 0; r < 4; r++) acc[mt][nt][r] = 0.f;

    // ---- prologue: chunk 0 -> stage 0 ----
    #pragma unroll
    for (int j = 0; j < 4; j++) {
        float4 f = *(const float4*)(FIg + goff[j]);
        float4 d = *(const float4*)(DIg + goff[j]);
        float4 s = make_float4(f.x + d.x, f.y + d.y, f.z + d.z, f.w + d.w);
        float4 t = make_float4(d.x - f.x, d.y - f.y, d.z - f.z, d.w - f.w);
        sts64(sbase + OSI + soff[j], pack2(s.y, s.x), pack2(s.w, s.z));
        sts64(sbase + OTI + soff[j], pack2(t.y, t.x), pack2(t.w, t.z));
    }
    if (!diag) {
        #pragma unroll
        for (int j = 0; j < 4; j++) {
            float4 f = *(const float4*)(FJg + goff[j]);
            float4 d = *(const float4*)(DJg + goff[j]);
            float4 s = make_float4(f.x + d.x, f.y + d.y, f.z + d.z, f.w + d.w);
            float4 t = make_float4(d.x - f.x, d.y - f.y, d.z - f.z, d.w - f.w);
            sts64(sbase + OSJ + soff[j], pack2(s.y, s.x), pack2(s.w, s.z));
            sts64(sbase + OTJ + soff[j], pack2(t.y, t.x), pack2(t.w, t.z));
        }
    }
    __syncthreads();

    // ---- main loop: one 32x32x64 warp-unit per chunk, producer interleaved ----
    for (int c = 0; c < NCH; c++) {
        const uint32_t stb  = sbase + (c & 1) * STG;
        const uint32_t nstb = sbase + ((c & 1) ^ 1) * STG;
        const uint32_t pA = stb + oA;
        const uint32_t pB = stb + oB;
        const bool more = (c + 1 < NCH);
        const int k1 = (c + 1) * KC;

        Frag f0, f1;
        ld_fr(pA, arow0, pB, brow0, 0,  lane, f0);
        ld_fr(pA, arow0, pB, brow0, 16, lane, f1);

        float4 rf[4], rd[4];
        if (more) {       // issue I-block loads
            #pragma unroll
            for (int j = 0; j < 4; j++) {
                rf[j] = *(const float4*)(FIg + goff[j] + k1);
                rd[j] = *(const float4*)(DIg + goff[j] + k1);
            }
        }
        mma_fr(acc, f0);
        ld_fr(pA, arow0, pB, brow0, 32, lane, f0);
        mma_fr(acc, f1);
        if (more) {       // store I-block; issue J-block loads
            #pragma unroll
            for (int j = 0; j < 4; j++) {
                float4 f = rf[j], d = rd[j];
                float4 s = make_float4(f.x + d.x, f.y + d.y, f.z + d.z, f.w + d.w);
                float4 t = make_float4(d.x - f.x, d.y - f.y, d.z - f.z, d.w - f.w);
                sts64(nstb + OSI + soff[j], pack2(s.y, s.x), pack2(s.w, s.z));
                sts64(nstb + OTI + soff[j], pack2(t.y, t.x), pack2(t.w, t.z));
            }
            if (!diag) {
                #pragma unroll
                for (int j = 0; j < 4; j++) {
                    rf[j] = *(const float4*)(FJg + goff[j] + k1);
                    rd[j] = *(const float4*)(DJg + goff[j] + k1);
                }
            }
        }
        ld_fr(pA, arow0, pB, brow0, 48, lane, f1);
        mma_fr(acc, f0);
        mma_fr(acc, f1);
        if (more && !diag) {
            #pragma unroll
            for (int j = 0; j < 4; j++) {
                float4 f = rf[j], d = rd[j];
                float4 s = make_float4(f.x + d.x, f.y + d.y, f.z + d.z, f.w + d.w);
                float4 t = make_float4(d.x - f.x, d.y - f.y, d.z - f.z, d.w - f.w);
                sts64(nstb + OSJ + soff[j], pack2(s.y, s.x), pack2(s.w, s.z));
                sts64(nstb + OTJ + soff[j], pack2(t.y, t.x), pack2(t.w, t.z));
            }
        }
        __syncthreads();
    }

    // ---- epilogue: pair P with Q^T via smem ----
    float* sP = (float*)smem;            // 64 x 65
    float* sQ = sP + 64 * 65;
    float* dst = role ? sQ : sP;
    const int quad = lane >> 2;
    const int tcol = (lane & 3) * 2;
    #pragma unroll
    for (int mt = 0; mt < 2; mt++) {
        #pragma unroll
        for (int nt = 0; nt < 4; nt++) {
            int r0 = arow0 + mt * 16 + quad;
            int c0 = brow0 + nt * 8 + tcol;
            dst[r0 * 65 + c0]           = acc[mt][nt][0];
            dst[r0 * 65 + c0 + 1]       = acc[mt][nt][1];
            dst[(r0 + 8) * 65 + c0]     = acc[mt][nt][2];
            dst[(r0 + 8) * 65 + c0 + 1] = acc[mt][nt][3];
        }
    }
    __syncthreads();

    float local = 0.f;
    #pragma unroll
    for (int i = 0; i < 16; i++) {
        int e = tid + i * 256;
        int r = e >> 6, cc = e & 63;
        float val = 0.5f * (sP[r * 65 + cc] + sQ[cc * 65 + r]);
        local = fmaf(val, val, local);
    }
    local *= w;

    red[tid] = local;
    __syncthreads();
    #pragma unroll
    for (int stp = 128; stp > 0; stp >>= 1) {
        if (tid < stp) red[tid] += red[tid + stp];
        __syncthreads();
    }

    if (tid == 0) {
        g_partials[b * NT2 + blockIdx.x] = red[0];
        __threadfence();
        unsigned int prev = atomicAdd(&g_count, 1u);
        s_islast = (prev == NPART - 1) ? 1u : 0u;
    }
    __syncthreads();
    if (s_islast) {
        __threadfence();
        float v = 0.f;
        for (int i = tid; i < NPART; i += 256) v += g_partials[i];
        red[tid] = v;
        __syncthreads();
        #pragma unroll
        for (int stp = 128; stp > 0; stp >>= 1) {
            if (tid < stp) red[tid] += red[tid + stp];
            __syncthreads();
        }
        if (tid == 0) {
            out[0] = red[0] * (1.0f / 1099511627776.0f);  // / 2^40
            g_count = 0;  // reset for next graph replay
        }
    }
}

extern "C" void kernel_launch(void* const* d_in, const int* in_sizes, int n_in,
                              void* d_out, int out_size) {
    const float* F = (const float*)d_in[0];   // feat
    const float* D = (const float*)d_in[1];   // feat_decod
    float* out = (float*)d_out;

    cudaFuncSetAttribute(gram_st_kernel, cudaFuncAttributeMaxDynamicSharedMemorySize, DYN_SMEM);
    dim3 grid(NT2, B_);
    gram_st_kernel<<<grid, 256, DYN_SMEM>>>(F, D, out);
}

// round 11
// speedup vs baseline: 1.4468x; 1.1863x over previous
#include <cuda_runtime.h>
#include <cuda_bf16.h>
#include <cstdint>

// GrahamLoss: 2-kernel S/T pipeline.
// A: S=bf16(F+D), T=bf16(D-F) streamed to gmem scratch.
// B: per 64x64 pair-tile (I<=J, 8x8 grid, x16 batches = 576 CTAs):
//    P=S_I T_J^T, Q=S_J T_I^T via bf16 mma.sync, panels fed by cp.async
//    (3-stage pipeline), pair P with Q^T in smem, square, reduce.
// loss = sum ((P+Q^T)/2)^2-style pairing / 2^40.

#define B_    16
#define C_    512
#define HW_   1024
#define NELT  ((size_t)B_ * C_ * HW_)   // 8388608
#define KC    64             // bf16 k per chunk
#define NCH   (HW_ / KC)     // 16
#define NT2   36
#define NPART (B_ * NT2)     // 576

// kernel B smem: 3 stages x 32KB (4 panels x 8KB: 64 rows x 128B swizzled)
#define OSI 0
#define OTI 8192
#define OSJ 16384
#define OTJ 24576
#define STG 32768
#define DYN_SMEM (3 * STG)   // 96 KB

__device__ __align__(16) __nv_bfloat16 g_S[NELT];   // 16.7 MB
__device__ __align__(16) __nv_bfloat16 g_T[NELT];   // 16.7 MB
__device__ float        g_partials[NPART];
__device__ unsigned int g_count;

__constant__ int c_u[NT2] = {0,0,0,0,0,0,0,0,1,1,1,1,1,1,1,2,2,2,2,2,2,3,3,3,3,3,4,4,4,4,5,5,5,6,6,7};
__constant__ int c_v[NT2] = {0,1,2,3,4,5,6,7,1,2,3,4,5,6,7,2,3,4,5,6,7,3,4,5,6,7,4,5,6,7,5,6,7,6,7,7};

// ---------- helpers ----------
__device__ __forceinline__ uint32_t smem_u32(const void* p) {
    uint32_t a;
    asm("{ .reg .u64 t; cvta.to.shared.u64 t, %1; cvt.u32.u64 %0, t; }" : "=r"(a) : "l"(p));
    return a;
}
// 128B-row panel address, bf16 col k in [0,64): 16B unit XOR row&7 (conflict-free)
__device__ __forceinline__ uint32_t paddr(uint32_t pbase, int row, int k) {
    return pbase + (uint32_t)row * 128u
         + ((((uint32_t)(k >> 3) ^ (uint32_t)row) & 7u) << 4) + ((uint32_t)(k & 7) << 1);
}
__device__ __forceinline__ uint32_t pack2(float hi, float lo) {
    uint32_t r;
    asm("cvt.rn.bf16x2.f32 %0, %1, %2;" : "=r"(r) : "f"(hi), "f"(lo));
    return r;
}
__device__ __forceinline__ void cp_async16(uint32_t dst, const void* src) {
    asm volatile("cp.async.cg.shared.global [%0], [%1], 16;" :: "r"(dst), "l"(src) : "memory");
}
__device__ __forceinline__ void cp_commit() { asm volatile("cp.async.commit_group;" ::: "memory"); }
template <int N>
__device__ __forceinline__ void cp_wait() { asm volatile("cp.async.wait_group %0;" :: "n"(N) : "memory"); }
__device__ __forceinline__ void ldm_x4(uint32_t* r, uint32_t addr) {
    asm volatile("ldmatrix.sync.aligned.m8n8.x4.shared.b16 {%0,%1,%2,%3}, [%4];"
                 : "=r"(r[0]), "=r"(r[1]), "=r"(r[2]), "=r"(r[3]) : "r"(addr));
}
__device__ __forceinline__ void mma_bf16(float* d, const uint32_t* a, const uint32_t* b) {
    asm volatile("mma.sync.aligned.m16n8k16.row.col.f32.bf16.bf16.f32 "
                 "{%0,%1,%2,%3}, {%4,%5,%6,%7}, {%8,%9}, {%0,%1,%2,%3};"
                 : "+f"(d[0]), "+f"(d[1]), "+f"(d[2]), "+f"(d[3])
                 : "r"(a[0]), "r"(a[1]), "r"(a[2]), "r"(a[3]), "r"(b[0]), "r"(b[1]));
}

struct Frag { uint32_t a[2][4]; uint32_t b[4][2]; };

__device__ __forceinline__ void ld_fr(uint32_t pA, int arow0, uint32_t pB, int brow0,
                                      int k0, int lane, Frag& f) {
    const int a_row = lane & 15;
    const int a_k   = (lane >> 4) << 3;
    ldm_x4(f.a[0], paddr(pA, arow0 + a_row,      k0 + a_k));
    ldm_x4(f.a[1], paddr(pA, arow0 + 16 + a_row, k0 + a_k));
    const int b_row = (((lane >> 4) & 1) << 3) + (lane & 7);
    const int b_k   = ((lane >> 3) & 1) << 3;
    #pragma unroll
    for (int tp = 0; tp < 2; tp++) {
        uint32_t t4[4];
        ldm_x4(t4, paddr(pB, brow0 + tp * 16 + b_row, k0 + b_k));
        f.b[2 * tp][0] = t4[0]; f.b[2 * tp][1] = t4[1];
        f.b[2 * tp + 1][0] = t4[2]; f.b[2 * tp + 1][1] = t4[3];
    }
}
__device__ __forceinline__ void mma_fr(float acc[2][4][4], const Frag& f) {
    #pragma unroll
    for (int mt = 0; mt < 2; mt++)
        #pragma unroll
        for (int nt = 0; nt < 4; nt++)
            mma_bf16(acc[mt][nt], f.a[mt], f.b[nt]);
}

// ---------- kernel A: S/T conversion ----------
__global__ __launch_bounds__(256)
void st_convert_kernel(const float* __restrict__ F, const float* __restrict__ Dm) {
    const size_t base = (size_t)blockIdx.x * 256 + threadIdx.x;
    const float4* F4 = (const float4*)F;
    const float4* D4 = (const float4*)Dm;
    uint2* S2 = (uint2*)g_S;
    uint2* T2 = (uint2*)g_T;
    #pragma unroll
    for (int k = 0; k < 8; k++) {
        size_t i = base + (size_t)k * 262144;   // 1024 blocks * 256 threads
        float4 f = F4[i];
        float4 d = D4[i];
        S2[i] = make_uint2(pack2(f.y + d.y, f.x + d.x), pack2(f.w + d.w, f.z + d.z));
        T2[i] = make_uint2(pack2(d.y - f.y, d.x - f.x), pack2(d.w - f.w, d.z - f.z));
    }
}

// ---------- kernel B: gram pair-tile ----------
__global__ __launch_bounds__(256, 2)
void gram_st_kernel(float* __restrict__ out) {
    extern __shared__ __align__(128) unsigned char smem[];
    __shared__ float red[256];
    __shared__ unsigned int s_islast;

    const int tid  = threadIdx.x;
    const int lane = tid & 31;
    const int wid  = tid >> 5;
    const int b    = blockIdx.y;
    const int I = c_u[blockIdx.x];
    const int J = c_v[blockIdx.x];
    const int diag = (I == J);
    const float w = diag ? 1.0f : 2.0f;

    const __nv_bfloat16* SIg = g_S + ((size_t)b * C_ + I * 64) * HW_;
    const __nv_bfloat16* TIg = g_T + ((size_t)b * C_ + I * 64) * HW_;
    const __nv_bfloat16* SJg = g_S + ((size_t)b * C_ + J * 64) * HW_;
    const __nv_bfloat16* TJg = g_T + ((size_t)b * C_ + J * 64) * HW_;

    const uint32_t sbase = smem_u32(smem);

    // warp roles: 0 => P = S_I T_J^T (T_I if diag), 1 => Q = S_J T_I^T
    const int role = wid >> 2;
    const int wq   = wid & 3;
    const int arow0 = (wq >> 1) * 32;
    const int brow0 = (wq & 1) * 32;
    const uint32_t oA = role ? (diag ? OSI : OSJ) : OSI;
    const uint32_t oB = role ? OTI : (diag ? OTI : OTJ);
    const bool active = !(role && diag);    // diag CTAs skip Q (P == Q there)

    // producer: slot = tid + j*256 (j<2) -> row = slot>>3 (0..63), u = slot&7
    const int prow = tid >> 3;              // +32 for j=1
    const int pu   = tid & 7;

    float acc[2][4][4];
    #pragma unroll
    for (int mt = 0; mt < 2; mt++)
        #pragma unroll
        for (int nt = 0; nt < 4; nt++)
            #pragma unroll
            for (int r = 0; r < 4; r++) acc[mt][nt][r] = 0.f;

    // issue one chunk's cp.asyncs into stage s
    auto issue = [&](int c) {
        const uint32_t stg = sbase + (uint32_t)(c % 3) * STG;
        const int kb = c * KC;              // bf16 column base
        #pragma unroll
        for (int j = 0; j < 2; j++) {
            int row = prow + j * 32;
            uint32_t so = (uint32_t)row * 128u + ((((uint32_t)pu ^ (uint32_t)row) & 7u) << 4);
            size_t gb = (size_t)row * HW_ + kb + pu * 8;
            cp_async16(stg + OSI + so, SIg + gb);
            cp_async16(stg + OTI + so, TIg + gb);
            if (!diag) {
                cp_async16(stg + OSJ + so, SJg + gb);
                cp_async16(stg + OTJ + so, TJg + gb);
            }
        }
        cp_commit();
    };

    // prologue: chunks 0,1
    issue(0);
    issue(1);

    for (int c = 0; c < NCH; c++) {
        if (c == NCH - 1) cp_wait<0>(); else cp_wait<1>();
        __syncthreads();
        if (c + 2 < NCH) issue(c + 2);

        if (active) {
            const uint32_t stb = sbase + (uint32_t)(c % 3) * STG;
            const uint32_t pA = stb + oA;
            const uint32_t pB = stb + oB;
            Frag f0, f1;
            ld_fr(pA, arow0, pB, brow0, 0,  lane, f0);
            ld_fr(pA, arow0, pB, brow0, 16, lane, f1);
            mma_fr(acc, f0);
            ld_fr(pA, arow0, pB, brow0, 32, lane, f0);
            mma_fr(acc, f1);
            ld_fr(pA, arow0, pB, brow0, 48, lane, f1);
            mma_fr(acc, f0);
            mma_fr(acc, f1);
        }
    }
    __syncthreads();   // all stages consumed; smem now reusable

    // ---- epilogue: pair P with Q^T via smem ----
    float* sP = (float*)smem;            // 64 x 65
    float* sQ = sP + 64 * 65;
    if (active) {
        float* dst = role ? sQ : sP;
        const int quad = lane >> 2;
        const int tcol = (lane & 3) * 2;
        #pragma unroll
        for (int mt = 0; mt < 2; mt++) {
            #pragma unroll
            for (int nt = 0; nt < 4; nt++) {
                int r0 = arow0 + mt * 16 + quad;
                int c0 = brow0 + nt * 8 + tcol;
                dst[r0 * 65 + c0]           = acc[mt][nt][0];
                dst[r0 * 65 + c0 + 1]       = acc[mt][nt][1];
                dst[(r0 + 8) * 65 + c0]     = acc[mt][nt][2];
                dst[(r0 + 8) * 65 + c0 + 1] = acc[mt][nt][3];
            }
        }
    }
    __syncthreads();

    float local = 0.f;
    #pragma unroll
    for (int i = 0; i < 16; i++) {
        int e = tid + i * 256;
        int r = e >> 6, cc = e & 63;
        float qt = diag ? sP[cc * 65 + r] : sQ[cc * 65 + r];
        float val = 0.5f * (sP[r * 65 + cc] + qt);
        local = fmaf(val, val, local);
    }
    local *= w;

    red[tid] = local;
    __syncthreads();
    #pragma unroll
    for (int stp = 128; stp > 0; stp >>= 1) {
        if (tid < stp) red[tid] += red[tid + stp];
        __syncthreads();
    }

    if (tid == 0) {
        g_partials[b * NT2 + blockIdx.x] = red[0];
        __threadfence();
        unsigned int prev = atomicAdd(&g_count, 1u);
        s_islast = (prev == NPART - 1) ? 1u : 0u;
    }
    __syncthreads();
    if (s_islast) {
        __threadfence();
        float v = 0.f;
        for (int i = tid; i < NPART; i += 256) v += g_partials[i];
        red[tid] = v;
        __syncthreads();
        #pragma unroll
        for (int stp = 128; stp > 0; stp >>= 1) {
            if (tid < stp) red[tid] += red[tid + stp];
            __syncthreads();
        }
        if (tid == 0) {
            out[0] = red[0] * (1.0f / 1099511627776.0f);  // / 2^40
            g_count = 0;  // reset for next graph replay
        }
    }
}

extern "C" void kernel_launch(void* const* d_in, const int* in_sizes, int n_in,
                              void* d_out, int out_size) {
    const float* F = (const float*)d_in[0];   // feat
    const float* D = (const float*)d_in[1];   // feat_decod
    float* out = (float*)d_out;

    cudaFuncSetAttribute(gram_st_kernel, cudaFuncAttributeMaxDynamicSharedMemorySize, DYN_SMEM);
    st_convert_kernel<<<1024, 256>>>(F, D);
    dim3 grid(NT2, B_);
    gram_st_kernel<<<grid, 256, DYN_SMEM>>>(out);
}